// round 16
// baseline (speedup 1.0000x reference)
#include <cuda_runtime.h>
#include <math.h>
#include <cstdint>

#define BATCH 4
#define CDIM 192
#define C3 576
#define HW 16384
#define H_IMG 128
#define W_IMG 128
#define HID 510
#define HID2 1020
#define HEADS 8
#define HDIM 24
#define QK 384            // q+k channels
#define NCHUNK 8          // attn-score pixel chunks
#define CHUNK (HW / NCHUNK)

// ---------------- scratch (static device globals; no allocs allowed) ---------
__device__ float2 g_stats[(size_t)BATCH * HW];         // per-pixel {mu, rstd}
__device__ float g_qkv[(size_t)BATCH * C3 * HW];       // qkv after 1x1
__device__ float g_qkv2[(size_t)BATCH * C3 * HW];      // qkv after dwconv
__device__ float g_part[(size_t)BATCH * QK * H_IMG];   // per-row partial sum-of-squares
__device__ float g_spart[(size_t)BATCH * HEADS * NCHUNK * HDIM * HDIM];
__device__ float g_attnmat[BATCH * HEADS * HDIM * HDIM];
__device__ float g_weff[BATCH * CDIM * CDIM];          // w_proj @ blockdiag(attn)
__device__ float g_x1[(size_t)BATCH * CDIM * HW];      // x + attn branch
__device__ float g_ffn[(size_t)BATCH * HID2 * HW];     // ffn-in GEMM out
__device__ float g_gate[(size_t)BATCH * HID * HW];     // fused dwconv+gelu-gate out

// ---------------- LN stats: per-pixel mean & rstd over channel dim -----------
__global__ __launch_bounds__(256) void ln_stats_kernel(
    const float* __restrict__ x, float2* __restrict__ stats)
{
    int b = blockIdx.y;
    int p = blockIdx.x * 256 + threadIdx.x;          // 0..HW-1
    const float* xb = x + (size_t)b * CDIM * HW + p;
    float s = 0.f, ss = 0.f;
    #pragma unroll 8
    for (int c = 0; c < CDIM; c++) {
        float v = xb[(size_t)c * HW];
        s += v; ss += v * v;
    }
    float mu  = s * (1.f / CDIM);
    float var = ss * (1.f / CDIM) - mu * mu;
    stats[(size_t)b * HW + p] = make_float2(mu, rsqrtf(var + 1e-5f));
}

// ---------------- fused-LN B element transform ------------------------------
__device__ __forceinline__ float4 ln_apply4(float4 v, const float2* st,
                                            float wk, float bk)
{
    v.x = (v.x - st[0].x) * st[0].y * wk + bk;
    v.y = (v.y - st[1].x) * st[1].y * wk + bk;
    v.z = (v.z - st[2].x) * st[2].y * wk + bk;
    v.w = (v.w - st[3].x) * st[3].y * wk + bk;
    return v;
}

// ---------------- 1x1 conv as SGEMM -----------------------------------------
// C[b][m][n] = sum_k A[b][m][k] * LN?(Bact[b][k][n]) (+R[b][m][n])
// Tile BM x 128(N) x 8(K), 256 threads, MT(=BM/8) x 4 microtile.
// Warp layout: tx = tid&31 (n = n0+tx*4), ty = tid>>5 (m = m0+ty*MT).
//   -> B fragment LDS.128 conflict-free; A fragment warp-broadcast;
//      As padded to BM+4 so A staging STS is conflict-free.
template<int BM, bool FUSE_LN>
__global__ __launch_bounds__(256) void gemm_kernel(
    const float* __restrict__ A, const float* __restrict__ Bact,
    float* __restrict__ Cout, const float* __restrict__ R,
    int M, int K, size_t aStride, size_t bStride,
    const float2* __restrict__ stats,
    const float* __restrict__ lnw, const float* __restrict__ lnb)
{
    constexpr int MT  = BM / 8;       // rows per thread (16 or 8)
    constexpr int TPM = 256 / BM;     // loader threads per A row (2 or 4)
    constexpr int APT = 8 / TPM;      // loader A elems per thread (4 or 2)
    constexpr int AP  = BM + 4;       // padded A row (272B / 528B: 16B-aligned)

    __shared__ float As[2][8][AP];
    __shared__ float Bs[2][8][128];

    const int b   = blockIdx.z;
    const int m0  = blockIdx.y * BM;
    const int n0  = blockIdx.x * 128;
    const int tid = threadIdx.x;
    const int tx  = tid & 31;        // n: n0 + tx*4
    const int ty  = tid >> 5;        // m: m0 + ty*MT
    const float* Ab = A + (size_t)b * aStride;
    const float* Bb = Bact + (size_t)b * bStride;

    const int a_m  = tid / TPM;            // 0..BM-1
    const int a_k0 = (tid % TPM) * APT;    // k offset
    const int b_k  = tid >> 5;             // 0..7
    const int b_n4 = (tid & 31) * 4;       // 0..124

    const float2* stp = FUSE_LN ? (stats + (size_t)b * HW + n0 + b_n4) : nullptr;
    float2 stl[4];
    if (FUSE_LN) {
        #pragma unroll
        for (int t = 0; t < 4; t++) stl[t] = stp[t];
    }

    const int nIter = (K + 7) / 8;

    float acc[MT][4] = {};
    float pa[APT];
    float4 pb;

    // ---- load tile 0 directly to smem buf 0 ----
    {
        int gm = m0 + a_m;
        #pragma unroll
        for (int t = 0; t < APT; t++) {
            int k = a_k0 + t;
            As[0][a_k0 + t][a_m] = (gm < M && k < K) ? Ab[(size_t)gm * K + k] : 0.f;
        }
        float4 v = make_float4(0.f, 0.f, 0.f, 0.f);
        if (b_k < K) {
            v = *reinterpret_cast<const float4*>(&Bb[(size_t)b_k * HW + n0 + b_n4]);
            if (FUSE_LN) v = ln_apply4(v, stl, lnw[b_k], lnb[b_k]);
        }
        *reinterpret_cast<float4*>(&Bs[0][b_k][b_n4]) = v;
    }
    __syncthreads();

    for (int it = 0; it < nIter; it++) {
        int cur = it & 1;
        int nxt = cur ^ 1;

        bool hasNext = (it + 1 < nIter);
        if (hasNext) {
            int k0 = (it + 1) * 8;
            int gm = m0 + a_m;
            #pragma unroll
            for (int t = 0; t < APT; t++) {
                int k = k0 + a_k0 + t;
                pa[t] = (gm < M && k < K) ? Ab[(size_t)gm * K + k] : 0.f;
            }
            int kb = k0 + b_k;
            pb = make_float4(0.f, 0.f, 0.f, 0.f);
            if (kb < K) {
                pb = *reinterpret_cast<const float4*>(&Bb[(size_t)kb * HW + n0 + b_n4]);
                if (FUSE_LN) pb = ln_apply4(pb, stl, lnw[kb], lnb[kb]);
            }
        }

        #pragma unroll
        for (int kk = 0; kk < 8; kk++) {
            float a[MT], bb[4];
            #pragma unroll
            for (int q4 = 0; q4 < MT / 4; q4++) {
                float4 av = *reinterpret_cast<const float4*>(&As[cur][kk][ty * MT + q4 * 4]);
                a[q4 * 4 + 0] = av.x; a[q4 * 4 + 1] = av.y;
                a[q4 * 4 + 2] = av.z; a[q4 * 4 + 3] = av.w;
            }
            float4 bv = *reinterpret_cast<const float4*>(&Bs[cur][kk][tx * 4]);
            bb[0] = bv.x; bb[1] = bv.y; bb[2] = bv.z; bb[3] = bv.w;
            #pragma unroll
            for (int i = 0; i < MT; i++)
                #pragma unroll
                for (int j = 0; j < 4; j++)
                    acc[i][j] += a[i] * bb[j];
        }

        if (hasNext) {
            #pragma unroll
            for (int t = 0; t < APT; t++)
                As[nxt][a_k0 + t][a_m] = pa[t];
            *reinterpret_cast<float4*>(&Bs[nxt][b_k][b_n4]) = pb;
            __syncthreads();
        }
    }

    // ---- epilogue ----
    #pragma unroll
    for (int i = 0; i < MT; i++) {
        int m = m0 + ty * MT + i;
        if (m >= M) continue;
        size_t base = (size_t)b * M * HW + (size_t)m * HW + n0 + tx * 4;
        if (R) {
            float4 r4 = *reinterpret_cast<const float4*>(&R[base]);
            float4 o = make_float4(acc[i][0] + r4.x, acc[i][1] + r4.y,
                                   acc[i][2] + r4.z, acc[i][3] + r4.w);
            *reinterpret_cast<float4*>(&Cout[base]) = o;
        } else {
            float4 o = make_float4(acc[i][0], acc[i][1], acc[i][2], acc[i][3]);
            *reinterpret_cast<float4*>(&Cout[base]) = o;
        }
    }
}

// ---------------- depthwise 3x3 SAME (qkv path), 2 rows/block ----------------
__global__ __launch_bounds__(128) void dwconv_kernel(
    const float* __restrict__ in, const float* __restrict__ w,
    float* __restrict__ out, float* __restrict__ part)
{
    int j  = threadIdx.x;          // col 0..127
    int r0 = blockIdx.x * 2;       // first of two rows
    int c  = blockIdx.y;           // channel (0..C3-1)
    int b  = blockIdx.z;
    const float* wp = w + c * 9;
    float wr[9];
    #pragma unroll
    for (int t = 0; t < 9; t++) wr[t] = __ldg(&wp[t]);
    const float* ip = in + ((size_t)b * C3 + c) * HW;

    float acc0 = 0.f, acc1 = 0.f;
    #pragma unroll
    for (int rr = -1; rr <= 2; rr++) {
        int ii = r0 + rr;
        if (ii < 0 || ii >= H_IMG) continue;
        float v[3];
        #pragma unroll
        for (int dx = -1; dx <= 1; dx++) {
            int jj = j + dx;
            v[dx + 1] = (jj >= 0 && jj < W_IMG) ? ip[ii * W_IMG + jj] : 0.f;
        }
        if (rr <= 1) {
            int t = (rr + 1) * 3;
            acc0 += wr[t] * v[0] + wr[t + 1] * v[1] + wr[t + 2] * v[2];
        }
        if (rr >= 0) {
            int t = rr * 3;
            acc1 += wr[t] * v[0] + wr[t + 1] * v[1] + wr[t + 2] * v[2];
        }
    }
    size_t obase = ((size_t)b * C3 + c) * HW;
    out[obase + (size_t)r0 * W_IMG + j]       = acc0;
    out[obase + (size_t)(r0 + 1) * W_IMG + j] = acc1;

    if (c < QK) {
        float s0 = acc0 * acc0;
        float s1 = acc1 * acc1;
        #pragma unroll
        for (int o = 16; o > 0; o >>= 1) {
            s0 += __shfl_down_sync(0xffffffffu, s0, o);
            s1 += __shfl_down_sync(0xffffffffu, s1, o);
        }
        __shared__ float red0[4], red1[4];
        if ((j & 31) == 0) { red0[j >> 5] = s0; red1[j >> 5] = s1; }
        __syncthreads();
        if (j == 0) {
            size_t pb = ((size_t)b * QK + c) * H_IMG;
            part[pb + r0]     = red0[0] + red0[1] + red0[2] + red0[3];
            part[pb + r0 + 1] = red1[0] + red1[1] + red1[2] + red1[3];
        }
    }
}

// ---------------- fused FFN: dwconv(c)&dwconv(c+HID) -> gelu*gate, 2 rows ----
__global__ __launch_bounds__(128) void dwconv_gate_kernel(
    const float* __restrict__ in, const float* __restrict__ w,
    float* __restrict__ out)
{
    int j  = threadIdx.x;          // col
    int r0 = blockIdx.x * 2;       // first of two rows
    int c  = blockIdx.y;           // 0..HID-1
    int b  = blockIdx.z;
    const float* wp1 = w + c * 9;
    const float* wp2 = w + (c + HID) * 9;
    float wr1[9], wr2[9];
    #pragma unroll
    for (int t = 0; t < 9; t++) { wr1[t] = __ldg(&wp1[t]); wr2[t] = __ldg(&wp2[t]); }
    const float* ip1 = in + ((size_t)b * HID2 + c) * HW;
    const float* ip2 = in + ((size_t)b * HID2 + c + HID) * HW;

    float a10 = 0.f, a11 = 0.f;
    float a20 = 0.f, a21 = 0.f;
    #pragma unroll
    for (int rr = -1; rr <= 2; rr++) {
        int ii = r0 + rr;
        if (ii < 0 || ii >= H_IMG) continue;
        float v1[3], v2[3];
        #pragma unroll
        for (int dx = -1; dx <= 1; dx++) {
            int jj = j + dx;
            bool ok = (jj >= 0 && jj < W_IMG);
            v1[dx + 1] = ok ? ip1[ii * W_IMG + jj] : 0.f;
            v2[dx + 1] = ok ? ip2[ii * W_IMG + jj] : 0.f;
        }
        if (rr <= 1) {
            int t = (rr + 1) * 3;
            a10 += wr1[t] * v1[0] + wr1[t + 1] * v1[1] + wr1[t + 2] * v1[2];
            a20 += wr2[t] * v2[0] + wr2[t + 1] * v2[1] + wr2[t + 2] * v2[2];
        }
        if (rr >= 0) {
            int t = rr * 3;
            a11 += wr1[t] * v1[0] + wr1[t + 1] * v1[1] + wr1[t + 2] * v1[2];
            a21 += wr2[t] * v2[0] + wr2[t + 1] * v2[1] + wr2[t + 2] * v2[2];
        }
    }
    float g0 = 0.5f * a10 * (1.f + erff(a10 * 0.70710678118654752f));
    float g1 = 0.5f * a11 * (1.f + erff(a11 * 0.70710678118654752f));
    size_t obase = ((size_t)b * HID + c) * HW;
    out[obase + (size_t)r0 * W_IMG + j]       = g0 * a20;
    out[obase + (size_t)(r0 + 1) * W_IMG + j] = g1 * a21;
}

// ---------------- attn score partials: 24x24 per (chunk,b,h) -----------------
// qs/ks rows padded to TP+1 = 65 floats: bank(c*65+t) = (c+t) mod 32 ->
// distinct banks across lanes' c values -> conflict-free inner product.
__global__ __launch_bounds__(576) void attn_score_partial_kernel(
    const float* __restrict__ qk, float* __restrict__ spart)
{
    const int TP = 64;
    int ch = blockIdx.x;             // chunk 0..NCHUNK-1
    int h  = blockIdx.y, b = blockIdx.z;
    __shared__ float qs[HDIM][TP + 1];
    __shared__ float ks[HDIM][TP + 1];
    int tid = threadIdx.x;           // 0..575
    int d = tid / HDIM, c = tid % HDIM;
    const float* qp = qk + ((size_t)b * C3 + h * HDIM) * HW;
    const float* kp = qk + ((size_t)b * C3 + CDIM + h * HDIM) * HW;
    int p_lo = ch * CHUNK;
    float acc = 0.f;
    for (int p0 = p_lo; p0 < p_lo + CHUNK; p0 += TP) {
        for (int idx = tid; idx < HDIM * TP; idx += 576) {
            int r = idx / TP, col = idx % TP;
            qs[r][col] = qp[(size_t)r * HW + p0 + col];
            ks[r][col] = kp[(size_t)r * HW + p0 + col];
        }
        __syncthreads();
        #pragma unroll 16
        for (int t = 0; t < TP; t++) acc += qs[d][t] * ks[c][t];
        __syncthreads();
    }
    spart[(((size_t)(b * HEADS + h) * NCHUNK + ch) * HDIM + d) * HDIM + c] = acc;
}

// ---------------- attn finish: norms + sum chunks + scale + softmax ----------
__global__ __launch_bounds__(576) void attn_finish_kernel(
    const float* __restrict__ spart, const float* __restrict__ part,
    const float* __restrict__ temp, float* __restrict__ attn)
{
    int h = blockIdx.x, b = blockIdx.y;
    __shared__ float sA[HDIM][HDIM + 1];
    __shared__ float sInvQ[HDIM], sInvK[HDIM];
    int tid = threadIdx.x;
    int d = tid / HDIM, c = tid % HDIM;

    // lanes 0..23: invq for this head's q channels; 24..47: invk
    if (tid < 2 * HDIM) {
        int isK = tid >= HDIM;
        int lane = isK ? (tid - HDIM) : tid;
        int chn = (isK ? CDIM : 0) + h * HDIM + lane;   // channel in [0, QK)
        const float* pp = part + ((size_t)b * QK + chn) * H_IMG;
        float ss = 0.f;
        #pragma unroll 8
        for (int r = 0; r < H_IMG; r++) ss += pp[r];
        float inv = 1.f / fmaxf(sqrtf(ss), 1e-12f);
        if (isK) sInvK[lane] = inv; else sInvQ[lane] = inv;
    }
    __syncthreads();

    const float* pp = spart + (((size_t)(b * HEADS + h) * NCHUNK) * HDIM + d) * HDIM + c;
    float acc = 0.f;
    #pragma unroll
    for (int ch = 0; ch < NCHUNK; ch++)
        acc += pp[(size_t)ch * HDIM * HDIM];
    sA[d][c] = acc * sInvQ[d] * sInvK[c] * temp[h];
    __syncthreads();
    if (tid < HDIM) {
        int row = tid;
        float mx = -1e30f;
        #pragma unroll
        for (int cc = 0; cc < HDIM; cc++) mx = fmaxf(mx, sA[row][cc]);
        float s = 0.f, e[HDIM];
        #pragma unroll
        for (int cc = 0; cc < HDIM; cc++) { e[cc] = expf(sA[row][cc] - mx); s += e[cc]; }
        float invs = 1.f / s;
        #pragma unroll
        for (int cc = 0; cc < HDIM; cc++)
            attn[((b * HEADS + h) * HDIM + row) * HDIM + cc] = e[cc] * invs;
    }
}

// ---------------- W_eff[b] = w_proj @ blockdiag(attn[b]) --------------------
__global__ __launch_bounds__(192) void weff_kernel(
    const float* __restrict__ wproj, const float* __restrict__ attn,
    float* __restrict__ weff)
{
    int m = blockIdx.x;       // 0..191
    int b = blockIdx.y;
    int n = threadIdx.x;      // 0..191
    int h = n / HDIM, c = n % HDIM;
    const float* wp = wproj + (size_t)m * CDIM + h * HDIM;
    const float* ap = attn + ((size_t)(b * HEADS + h) * HDIM) * HDIM + c;
    float s = 0.f;
    #pragma unroll
    for (int d = 0; d < HDIM; d++)
        s += wp[d] * ap[(size_t)d * HDIM];
    weff[((size_t)b * CDIM + m) * CDIM + n] = s;
}

// ---------------- host orchestration ----------------------------------------
extern "C" void kernel_launch(void* const* d_in, const int* in_sizes, int n_in,
                              void* d_out, int out_size)
{
    const float* x        = (const float*)d_in[0];
    const float* temp     = (const float*)d_in[1];
    const float* ln1_w    = (const float*)d_in[2];
    const float* ln1_b    = (const float*)d_in[3];
    const float* ln2_w    = (const float*)d_in[4];
    const float* ln2_b    = (const float*)d_in[5];
    const float* w_qkv    = (const float*)d_in[6];
    const float* w_qkv_dw = (const float*)d_in[7];
    const float* w_proj   = (const float*)d_in[8];
    const float* w_in     = (const float*)d_in[9];
    const float* w_dw     = (const float*)d_in[10];
    const float* w_out    = (const float*)d_in[11];
    float* out = (float*)d_out;

    float2* p_stats;
    float *p_qkv, *p_qkv2, *p_part, *p_spart, *p_attnmat, *p_weff,
          *p_x1, *p_ffn, *p_gate;
    cudaGetSymbolAddress((void**)&p_stats,   g_stats);
    cudaGetSymbolAddress((void**)&p_qkv,     g_qkv);
    cudaGetSymbolAddress((void**)&p_qkv2,    g_qkv2);
    cudaGetSymbolAddress((void**)&p_part,    g_part);
    cudaGetSymbolAddress((void**)&p_spart,   g_spart);
    cudaGetSymbolAddress((void**)&p_attnmat, g_attnmat);
    cudaGetSymbolAddress((void**)&p_weff,    g_weff);
    cudaGetSymbolAddress((void**)&p_x1,      g_x1);
    cudaGetSymbolAddress((void**)&p_ffn,     g_ffn);
    cudaGetSymbolAddress((void**)&p_gate,    g_gate);

    dim3 lnGrid(HW / 256, BATCH);

    // ---- attention branch ----
    ln_stats_kernel<<<lnGrid, 256>>>(x, p_stats);

    // qkv = w_qkv @ LN1(x)
    gemm_kernel<64, true><<<dim3(HW / 128, C3 / 64, BATCH), 256>>>(
        w_qkv, x, p_qkv, nullptr, C3, CDIM, 0, (size_t)CDIM * HW,
        p_stats, ln1_w, ln1_b);

    dwconv_kernel<<<dim3(H_IMG / 2, C3, BATCH), 128>>>(p_qkv, w_qkv_dw, p_qkv2, p_part);

    attn_score_partial_kernel<<<dim3(NCHUNK, HEADS, BATCH), 576>>>(p_qkv2, p_spart);

    attn_finish_kernel<<<dim3(HEADS, BATCH), 576>>>(p_spart, p_part, temp, p_attnmat);

    weff_kernel<<<dim3(CDIM, BATCH), 192>>>(w_proj, p_attnmat, p_weff);

    // x1 = W_eff[b] @ v + x   (v = channels [2*CDIM, 3*CDIM) of qkv2)
    gemm_kernel<64, false><<<dim3(HW / 128, CDIM / 64, BATCH), 256>>>(
        p_weff, p_qkv2 + (size_t)2 * CDIM * HW, p_x1, x, CDIM, CDIM,
        (size_t)CDIM * CDIM, (size_t)C3 * HW, nullptr, nullptr, nullptr);

    // ---- FFN branch ----
    ln_stats_kernel<<<lnGrid, 256>>>(p_x1, p_stats);

    // ffn = w_in @ LN2(x1)
    gemm_kernel<128, true><<<dim3(HW / 128, (HID2 + 127) / 128, BATCH), 256>>>(
        w_in, p_x1, p_ffn, nullptr, HID2, CDIM, 0, (size_t)CDIM * HW,
        p_stats, ln2_w, ln2_b);

    dwconv_gate_kernel<<<dim3(H_IMG / 2, HID, BATCH), 128>>>(p_ffn, w_dw, p_gate);

    gemm_kernel<64, false><<<dim3(HW / 128, CDIM / 64, BATCH), 256>>>(
        w_out, p_gate, out, p_x1, CDIM, HID, 0, (size_t)HID * HW,
        nullptr, nullptr, nullptr);
}

// round 17
// speedup vs baseline: 1.0068x; 1.0068x over previous
#include <cuda_runtime.h>
#include <math.h>
#include <cstdint>

#define BATCH 4
#define CDIM 192
#define C3 576
#define HW 16384
#define H_IMG 128
#define W_IMG 128
#define HID 510
#define HID2 1020
#define HEADS 8
#define HDIM 24
#define QK 384            // q+k channels
#define NCHUNK 8          // attn-score pixel chunks
#define CHUNK (HW / NCHUNK)

// ---------------- scratch (static device globals; no allocs allowed) ---------
__device__ float2 g_stats[(size_t)BATCH * HW];         // per-pixel {mu, rstd}
__device__ float g_qkv[(size_t)BATCH * C3 * HW];       // qkv after 1x1
__device__ float g_qkv2[(size_t)BATCH * C3 * HW];      // qkv after dwconv
__device__ float g_part[(size_t)BATCH * QK * H_IMG];   // per-row partial sum-of-squares
__device__ float g_spart[(size_t)BATCH * HEADS * NCHUNK * HDIM * HDIM];
__device__ float g_attnmat[BATCH * HEADS * HDIM * HDIM];
__device__ float g_weff[BATCH * CDIM * CDIM];          // w_proj @ blockdiag(attn)
__device__ float g_x1[(size_t)BATCH * CDIM * HW];      // x + attn branch
__device__ float g_ffn[(size_t)BATCH * HID2 * HW];     // ffn-in GEMM out
__device__ float g_gate[(size_t)BATCH * HID * HW];     // fused dwconv+gelu-gate out

// ---------------- LN stats: per-pixel mean & rstd over channel dim -----------
__global__ __launch_bounds__(256) void ln_stats_kernel(
    const float* __restrict__ x, float2* __restrict__ stats)
{
    int b = blockIdx.y;
    int p = blockIdx.x * 256 + threadIdx.x;          // 0..HW-1
    const float* xb = x + (size_t)b * CDIM * HW + p;
    float s = 0.f, ss = 0.f;
    #pragma unroll 8
    for (int c = 0; c < CDIM; c++) {
        float v = xb[(size_t)c * HW];
        s += v; ss += v * v;
    }
    float mu  = s * (1.f / CDIM);
    float var = ss * (1.f / CDIM) - mu * mu;
    stats[(size_t)b * HW + p] = make_float2(mu, rsqrtf(var + 1e-5f));
}

// ---------------- fused-LN B element transform ------------------------------
__device__ __forceinline__ float4 ln_apply4(float4 v, const float2* st,
                                            float wk, float bk)
{
    v.x = (v.x - st[0].x) * st[0].y * wk + bk;
    v.y = (v.y - st[1].x) * st[1].y * wk + bk;
    v.z = (v.z - st[2].x) * st[2].y * wk + bk;
    v.w = (v.w - st[3].x) * st[3].y * wk + bk;
    return v;
}

// ---------------- 1x1 conv as SGEMM -----------------------------------------
// C[b][m][n] = sum_k A[b][m][k] * LN?(Bact[b][k][n]) (+R[b][m][n])
// Tile BM x 128(N) x 8(K), 256 threads, MT(=BM/8) x 4 microtile.
// Warp layout: tx = tid&31 (n = n0+tx*4), ty = tid>>5 (m = m0+ty*MT).
//   -> B fragment LDS.128 conflict-free; A fragment warp-broadcast;
//      As padded to BM+4 so A staging STS is conflict-free.
// MINB: minimum CTAs/SM hint (2 for BM=64: ~80 regs, far under the 128 cap).
template<int BM, bool FUSE_LN, int MINB>
__global__ __launch_bounds__(256, MINB) void gemm_kernel(
    const float* __restrict__ A, const float* __restrict__ Bact,
    float* __restrict__ Cout, const float* __restrict__ R,
    int M, int K, size_t aStride, size_t bStride,
    const float2* __restrict__ stats,
    const float* __restrict__ lnw, const float* __restrict__ lnb)
{
    constexpr int MT  = BM / 8;       // rows per thread (16 or 8)
    constexpr int TPM = 256 / BM;     // loader threads per A row (2 or 4)
    constexpr int APT = 8 / TPM;      // loader A elems per thread (4 or 2)
    constexpr int AP  = BM + 4;       // padded A row (272B / 528B: 16B-aligned)

    __shared__ float As[2][8][AP];
    __shared__ float Bs[2][8][128];

    const int b   = blockIdx.z;
    const int m0  = blockIdx.y * BM;
    const int n0  = blockIdx.x * 128;
    const int tid = threadIdx.x;
    const int tx  = tid & 31;        // n: n0 + tx*4
    const int ty  = tid >> 5;        // m: m0 + ty*MT
    const float* Ab = A + (size_t)b * aStride;
    const float* Bb = Bact + (size_t)b * bStride;

    const int a_m  = tid / TPM;            // 0..BM-1
    const int a_k0 = (tid % TPM) * APT;    // k offset
    const int b_k  = tid >> 5;             // 0..7
    const int b_n4 = (tid & 31) * 4;       // 0..124

    const float2* stp = FUSE_LN ? (stats + (size_t)b * HW + n0 + b_n4) : nullptr;
    float2 stl[4];
    if (FUSE_LN) {
        #pragma unroll
        for (int t = 0; t < 4; t++) stl[t] = stp[t];
    }

    const int nIter = (K + 7) / 8;

    float acc[MT][4] = {};
    float pa[APT];
    float4 pb;

    // ---- load tile 0 directly to smem buf 0 ----
    {
        int gm = m0 + a_m;
        #pragma unroll
        for (int t = 0; t < APT; t++) {
            int k = a_k0 + t;
            As[0][a_k0 + t][a_m] = (gm < M && k < K) ? Ab[(size_t)gm * K + k] : 0.f;
        }
        float4 v = make_float4(0.f, 0.f, 0.f, 0.f);
        if (b_k < K) {
            v = *reinterpret_cast<const float4*>(&Bb[(size_t)b_k * HW + n0 + b_n4]);
            if (FUSE_LN) v = ln_apply4(v, stl, lnw[b_k], lnb[b_k]);
        }
        *reinterpret_cast<float4*>(&Bs[0][b_k][b_n4]) = v;
    }
    __syncthreads();

    for (int it = 0; it < nIter; it++) {
        int cur = it & 1;
        int nxt = cur ^ 1;

        bool hasNext = (it + 1 < nIter);
        if (hasNext) {
            int k0 = (it + 1) * 8;
            int gm = m0 + a_m;
            #pragma unroll
            for (int t = 0; t < APT; t++) {
                int k = k0 + a_k0 + t;
                pa[t] = (gm < M && k < K) ? Ab[(size_t)gm * K + k] : 0.f;
            }
            int kb = k0 + b_k;
            pb = make_float4(0.f, 0.f, 0.f, 0.f);
            if (kb < K) {
                pb = *reinterpret_cast<const float4*>(&Bb[(size_t)kb * HW + n0 + b_n4]);
                if (FUSE_LN) pb = ln_apply4(pb, stl, lnw[kb], lnb[kb]);
            }
        }

        #pragma unroll
        for (int kk = 0; kk < 8; kk++) {
            float a[MT], bb[4];
            #pragma unroll
            for (int q4 = 0; q4 < MT / 4; q4++) {
                float4 av = *reinterpret_cast<const float4*>(&As[cur][kk][ty * MT + q4 * 4]);
                a[q4 * 4 + 0] = av.x; a[q4 * 4 + 1] = av.y;
                a[q4 * 4 + 2] = av.z; a[q4 * 4 + 3] = av.w;
            }
            float4 bv = *reinterpret_cast<const float4*>(&Bs[cur][kk][tx * 4]);
            bb[0] = bv.x; bb[1] = bv.y; bb[2] = bv.z; bb[3] = bv.w;
            #pragma unroll
            for (int i = 0; i < MT; i++)
                #pragma unroll
                for (int j = 0; j < 4; j++)
                    acc[i][j] += a[i] * bb[j];
        }

        if (hasNext) {
            #pragma unroll
            for (int t = 0; t < APT; t++)
                As[nxt][a_k0 + t][a_m] = pa[t];
            *reinterpret_cast<float4*>(&Bs[nxt][b_k][b_n4]) = pb;
            __syncthreads();
        }
    }

    // ---- epilogue ----
    #pragma unroll
    for (int i = 0; i < MT; i++) {
        int m = m0 + ty * MT + i;
        if (m >= M) continue;
        size_t base = (size_t)b * M * HW + (size_t)m * HW + n0 + tx * 4;
        if (R) {
            float4 r4 = *reinterpret_cast<const float4*>(&R[base]);
            float4 o = make_float4(acc[i][0] + r4.x, acc[i][1] + r4.y,
                                   acc[i][2] + r4.z, acc[i][3] + r4.w);
            *reinterpret_cast<float4*>(&Cout[base]) = o;
        } else {
            float4 o = make_float4(acc[i][0], acc[i][1], acc[i][2], acc[i][3]);
            *reinterpret_cast<float4*>(&Cout[base]) = o;
        }
    }
}

// ---------------- depthwise 3x3 SAME (qkv path), 2 rows/block ----------------
__global__ __launch_bounds__(128) void dwconv_kernel(
    const float* __restrict__ in, const float* __restrict__ w,
    float* __restrict__ out, float* __restrict__ part)
{
    int j  = threadIdx.x;          // col 0..127
    int r0 = blockIdx.x * 2;       // first of two rows
    int c  = blockIdx.y;           // channel (0..C3-1)
    int b  = blockIdx.z;
    const float* wp = w + c * 9;
    float wr[9];
    #pragma unroll
    for (int t = 0; t < 9; t++) wr[t] = __ldg(&wp[t]);
    const float* ip = in + ((size_t)b * C3 + c) * HW;

    float acc0 = 0.f, acc1 = 0.f;
    #pragma unroll
    for (int rr = -1; rr <= 2; rr++) {
        int ii = r0 + rr;
        if (ii < 0 || ii >= H_IMG) continue;
        float v[3];
        #pragma unroll
        for (int dx = -1; dx <= 1; dx++) {
            int jj = j + dx;
            v[dx + 1] = (jj >= 0 && jj < W_IMG) ? ip[ii * W_IMG + jj] : 0.f;
        }
        if (rr <= 1) {
            int t = (rr + 1) * 3;
            acc0 += wr[t] * v[0] + wr[t + 1] * v[1] + wr[t + 2] * v[2];
        }
        if (rr >= 0) {
            int t = rr * 3;
            acc1 += wr[t] * v[0] + wr[t + 1] * v[1] + wr[t + 2] * v[2];
        }
    }
    size_t obase = ((size_t)b * C3 + c) * HW;
    out[obase + (size_t)r0 * W_IMG + j]       = acc0;
    out[obase + (size_t)(r0 + 1) * W_IMG + j] = acc1;

    if (c < QK) {
        float s0 = acc0 * acc0;
        float s1 = acc1 * acc1;
        #pragma unroll
        for (int o = 16; o > 0; o >>= 1) {
            s0 += __shfl_down_sync(0xffffffffu, s0, o);
            s1 += __shfl_down_sync(0xffffffffu, s1, o);
        }
        __shared__ float red0[4], red1[4];
        if ((j & 31) == 0) { red0[j >> 5] = s0; red1[j >> 5] = s1; }
        __syncthreads();
        if (j == 0) {
            size_t pb = ((size_t)b * QK + c) * H_IMG;
            part[pb + r0]     = red0[0] + red0[1] + red0[2] + red0[3];
            part[pb + r0 + 1] = red1[0] + red1[1] + red1[2] + red1[3];
        }
    }
}

// ---------------- fused FFN: dwconv(c)&dwconv(c+HID) -> gelu*gate, 2 rows ----
__global__ __launch_bounds__(128) void dwconv_gate_kernel(
    const float* __restrict__ in, const float* __restrict__ w,
    float* __restrict__ out)
{
    int j  = threadIdx.x;          // col
    int r0 = blockIdx.x * 2;       // first of two rows
    int c  = blockIdx.y;           // 0..HID-1
    int b  = blockIdx.z;
    const float* wp1 = w + c * 9;
    const float* wp2 = w + (c + HID) * 9;
    float wr1[9], wr2[9];
    #pragma unroll
    for (int t = 0; t < 9; t++) { wr1[t] = __ldg(&wp1[t]); wr2[t] = __ldg(&wp2[t]); }
    const float* ip1 = in + ((size_t)b * HID2 + c) * HW;
    const float* ip2 = in + ((size_t)b * HID2 + c + HID) * HW;

    float a10 = 0.f, a11 = 0.f;
    float a20 = 0.f, a21 = 0.f;
    #pragma unroll
    for (int rr = -1; rr <= 2; rr++) {
        int ii = r0 + rr;
        if (ii < 0 || ii >= H_IMG) continue;
        float v1[3], v2[3];
        #pragma unroll
        for (int dx = -1; dx <= 1; dx++) {
            int jj = j + dx;
            bool ok = (jj >= 0 && jj < W_IMG);
            v1[dx + 1] = ok ? ip1[ii * W_IMG + jj] : 0.f;
            v2[dx + 1] = ok ? ip2[ii * W_IMG + jj] : 0.f;
        }
        if (rr <= 1) {
            int t = (rr + 1) * 3;
            a10 += wr1[t] * v1[0] + wr1[t + 1] * v1[1] + wr1[t + 2] * v1[2];
            a20 += wr2[t] * v2[0] + wr2[t + 1] * v2[1] + wr2[t + 2] * v2[2];
        }
        if (rr >= 0) {
            int t = rr * 3;
            a11 += wr1[t] * v1[0] + wr1[t + 1] * v1[1] + wr1[t + 2] * v1[2];
            a21 += wr2[t] * v2[0] + wr2[t + 1] * v2[1] + wr2[t + 2] * v2[2];
        }
    }
    float g0 = 0.5f * a10 * (1.f + erff(a10 * 0.70710678118654752f));
    float g1 = 0.5f * a11 * (1.f + erff(a11 * 0.70710678118654752f));
    size_t obase = ((size_t)b * HID + c) * HW;
    out[obase + (size_t)r0 * W_IMG + j]       = g0 * a20;
    out[obase + (size_t)(r0 + 1) * W_IMG + j] = g1 * a21;
}

// ---------------- attn score partials: 24x24 per (chunk,b,h) -----------------
// Double-buffered: prefetch tile it+1 into registers while computing tile it.
// qs/ks rows padded to TP+1 = 65 floats: bank(c*65+t) = (c+t) mod 32 ->
// conflict-free scalar LDS in the inner product. One barrier per tile.
__global__ __launch_bounds__(576) void attn_score_partial_kernel(
    const float* __restrict__ qk, float* __restrict__ spart)
{
    const int TP = 64;
    const int ELEMS = HDIM * TP;     // 1536 per array
    int ch = blockIdx.x;             // chunk 0..NCHUNK-1
    int h  = blockIdx.y, b = blockIdx.z;
    __shared__ float qs[2][HDIM][TP + 1];
    __shared__ float ks[2][HDIM][TP + 1];
    int tid = threadIdx.x;           // 0..575
    int d = tid / HDIM, c = tid % HDIM;
    const float* qp = qk + ((size_t)b * C3 + h * HDIM) * HW;
    const float* kp = qk + ((size_t)b * C3 + CDIM + h * HDIM) * HW;
    int p_lo = ch * CHUNK;
    const int NT = CHUNK / TP;       // 32 tiles

    // fill tile 0 into buffer 0
    for (int idx = tid; idx < ELEMS; idx += 576) {
        int r = idx / TP, col = idx % TP;
        qs[0][r][col] = qp[(size_t)r * HW + p_lo + col];
        ks[0][r][col] = kp[(size_t)r * HW + p_lo + col];
    }
    __syncthreads();

    float acc = 0.f;
    for (int it = 0; it < NT; it++) {
        int cur = it & 1, nxt = cur ^ 1;
        float pq[3], pk[3];
        bool hasNext = (it + 1 < NT);
        if (hasNext) {
            int p0 = p_lo + (it + 1) * TP;
            #pragma unroll
            for (int t = 0; t < 3; t++) {
                int idx = tid + t * 576;
                if (idx < ELEMS) {
                    int r = idx / TP, col = idx % TP;
                    pq[t] = qp[(size_t)r * HW + p0 + col];
                    pk[t] = kp[(size_t)r * HW + p0 + col];
                }
            }
        }
        #pragma unroll 16
        for (int t = 0; t < TP; t++) acc += qs[cur][d][t] * ks[cur][c][t];
        if (hasNext) {
            #pragma unroll
            for (int t = 0; t < 3; t++) {
                int idx = tid + t * 576;
                if (idx < ELEMS) {
                    int r = idx / TP, col = idx % TP;
                    qs[nxt][r][col] = pq[t];
                    ks[nxt][r][col] = pk[t];
                }
            }
        }
        __syncthreads();
    }
    spart[(((size_t)(b * HEADS + h) * NCHUNK + ch) * HDIM + d) * HDIM + c] = acc;
}

// ---------------- attn finish: norms + sum chunks + scale + softmax ----------
__global__ __launch_bounds__(576) void attn_finish_kernel(
    const float* __restrict__ spart, const float* __restrict__ part,
    const float* __restrict__ temp, float* __restrict__ attn)
{
    int h = blockIdx.x, b = blockIdx.y;
    __shared__ float sA[HDIM][HDIM + 1];
    __shared__ float sInvQ[HDIM], sInvK[HDIM];
    int tid = threadIdx.x;
    int d = tid / HDIM, c = tid % HDIM;

    // lanes 0..23: invq for this head's q channels; 24..47: invk
    if (tid < 2 * HDIM) {
        int isK = tid >= HDIM;
        int lane = isK ? (tid - HDIM) : tid;
        int chn = (isK ? CDIM : 0) + h * HDIM + lane;   // channel in [0, QK)
        const float* pp = part + ((size_t)b * QK + chn) * H_IMG;
        float ss = 0.f;
        #pragma unroll 8
        for (int r = 0; r < H_IMG; r++) ss += pp[r];
        float inv = 1.f / fmaxf(sqrtf(ss), 1e-12f);
        if (isK) sInvK[lane] = inv; else sInvQ[lane] = inv;
    }
    __syncthreads();

    const float* pp = spart + (((size_t)(b * HEADS + h) * NCHUNK) * HDIM + d) * HDIM + c;
    float acc = 0.f;
    #pragma unroll
    for (int ch = 0; ch < NCHUNK; ch++)
        acc += pp[(size_t)ch * HDIM * HDIM];
    sA[d][c] = acc * sInvQ[d] * sInvK[c] * temp[h];
    __syncthreads();
    if (tid < HDIM) {
        int row = tid;
        float mx = -1e30f;
        #pragma unroll
        for (int cc = 0; cc < HDIM; cc++) mx = fmaxf(mx, sA[row][cc]);
        float s = 0.f, e[HDIM];
        #pragma unroll
        for (int cc = 0; cc < HDIM; cc++) { e[cc] = expf(sA[row][cc] - mx); s += e[cc]; }
        float invs = 1.f / s;
        #pragma unroll
        for (int cc = 0; cc < HDIM; cc++)
            attn[((b * HEADS + h) * HDIM + row) * HDIM + cc] = e[cc] * invs;
    }
}

// ---------------- W_eff[b] = w_proj @ blockdiag(attn[b]) --------------------
__global__ __launch_bounds__(192) void weff_kernel(
    const float* __restrict__ wproj, const float* __restrict__ attn,
    float* __restrict__ weff)
{
    int m = blockIdx.x;       // 0..191
    int b = blockIdx.y;
    int n = threadIdx.x;      // 0..191
    int h = n / HDIM, c = n % HDIM;
    const float* wp = wproj + (size_t)m * CDIM + h * HDIM;
    const float* ap = attn + ((size_t)(b * HEADS + h) * HDIM) * HDIM + c;
    float s = 0.f;
    #pragma unroll
    for (int d = 0; d < HDIM; d++)
        s += wp[d] * ap[(size_t)d * HDIM];
    weff[((size_t)b * CDIM + m) * CDIM + n] = s;
}

// ---------------- host orchestration ----------------------------------------
extern "C" void kernel_launch(void* const* d_in, const int* in_sizes, int n_in,
                              void* d_out, int out_size)
{
    const float* x        = (const float*)d_in[0];
    const float* temp     = (const float*)d_in[1];
    const float* ln1_w    = (const float*)d_in[2];
    const float* ln1_b    = (const float*)d_in[3];
    const float* ln2_w    = (const float*)d_in[4];
    const float* ln2_b    = (const float*)d_in[5];
    const float* w_qkv    = (const float*)d_in[6];
    const float* w_qkv_dw = (const float*)d_in[7];
    const float* w_proj   = (const float*)d_in[8];
    const float* w_in     = (const float*)d_in[9];
    const float* w_dw     = (const float*)d_in[10];
    const float* w_out    = (const float*)d_in[11];
    float* out = (float*)d_out;

    float2* p_stats;
    float *p_qkv, *p_qkv2, *p_part, *p_spart, *p_attnmat, *p_weff,
          *p_x1, *p_ffn, *p_gate;
    cudaGetSymbolAddress((void**)&p_stats,   g_stats);
    cudaGetSymbolAddress((void**)&p_qkv,     g_qkv);
    cudaGetSymbolAddress((void**)&p_qkv2,    g_qkv2);
    cudaGetSymbolAddress((void**)&p_part,    g_part);
    cudaGetSymbolAddress((void**)&p_spart,   g_spart);
    cudaGetSymbolAddress((void**)&p_attnmat, g_attnmat);
    cudaGetSymbolAddress((void**)&p_weff,    g_weff);
    cudaGetSymbolAddress((void**)&p_x1,      g_x1);
    cudaGetSymbolAddress((void**)&p_ffn,     g_ffn);
    cudaGetSymbolAddress((void**)&p_gate,    g_gate);

    dim3 lnGrid(HW / 256, BATCH);

    // ---- attention branch ----
    ln_stats_kernel<<<lnGrid, 256>>>(x, p_stats);

    // qkv = w_qkv @ LN1(x)
    gemm_kernel<64, true, 2><<<dim3(HW / 128, C3 / 64, BATCH), 256>>>(
        w_qkv, x, p_qkv, nullptr, C3, CDIM, 0, (size_t)CDIM * HW,
        p_stats, ln1_w, ln1_b);

    dwconv_kernel<<<dim3(H_IMG / 2, C3, BATCH), 128>>>(p_qkv, w_qkv_dw, p_qkv2, p_part);

    attn_score_partial_kernel<<<dim3(NCHUNK, HEADS, BATCH), 576>>>(p_qkv2, p_spart);

    attn_finish_kernel<<<dim3(HEADS, BATCH), 576>>>(p_spart, p_part, temp, p_attnmat);

    weff_kernel<<<dim3(CDIM, BATCH), 192>>>(w_proj, p_attnmat, p_weff);

    // x1 = W_eff[b] @ v + x   (v = channels [2*CDIM, 3*CDIM) of qkv2)
    gemm_kernel<64, false, 2><<<dim3(HW / 128, CDIM / 64, BATCH), 256>>>(
        p_weff, p_qkv2 + (size_t)2 * CDIM * HW, p_x1, x, CDIM, CDIM,
        (size_t)CDIM * CDIM, (size_t)C3 * HW, nullptr, nullptr, nullptr);

    // ---- FFN branch ----
    ln_stats_kernel<<<lnGrid, 256>>>(p_x1, p_stats);

    // ffn = w_in @ LN2(x1)
    gemm_kernel<128, true, 1><<<dim3(HW / 128, (HID2 + 127) / 128, BATCH), 256>>>(
        w_in, p_x1, p_ffn, nullptr, HID2, CDIM, 0, (size_t)CDIM * HW,
        p_stats, ln2_w, ln2_b);

    dwconv_gate_kernel<<<dim3(H_IMG / 2, HID, BATCH), 128>>>(p_ffn, w_dw, p_gate);

    gemm_kernel<64, false, 2><<<dim3(HW / 128, CDIM / 64, BATCH), 256>>>(
        w_out, p_gate, out, p_x1, CDIM, HID, 0, (size_t)HID * HW,
        nullptr, nullptr, nullptr);
}